// round 11
// baseline (speedup 1.0000x reference)
#include <cuda_runtime.h>
#include <cuda_fp16.h>
#include <cstdint>

#define MM 256
#define OO 8192
#define II 8192
#define NNZ_TOTAL 3350528
#define NBUCKET 256          // 32-wide k buckets
#define NITER 64             // II / 128
#define STAGES 3
#define STAGE_BYTES 65536    // A 32KB + B 32KB
#define SMEM_BYTES (STAGES * STAGE_BYTES)   // 196608

__device__ __half         g_xh[MM * II];
__device__ unsigned short g_rk[NNZ_TOTAL];
__device__ __half         g_rv[NNZ_TOTAL];
__device__ int            g_roff[OO * (NBUCKET + 1)];
__device__ int            g_mode;   // 0=f16, 1=bf16, 2=f32

__device__ __forceinline__ uint32_t smem_u32(const void* p) {
    uint32_t a;
    asm("{ .reg .u64 t; cvta.to.shared.u64 t, %1; cvt.u32.u64 %0, t; }" : "=r"(a) : "l"(p));
    return a;
}
__device__ __forceinline__ uint32_t sw(uint32_t off) { return off ^ ((off >> 3) & 0x70u); }
// one packed int32 holds ONE byte: low nibble -> even k, high nibble -> odd k; (value-8) exact in f16
__device__ __forceinline__ uint32_t dq(uint32_t v) {
    uint32_t h = 0x64006400u | (v & 0xFu) | ((v << 12) & 0x000F0000u);
    __half2 a = *reinterpret_cast<__half2*>(&h);
    uint32_t c8 = 0x64086408u;
    __half2 b = *reinterpret_cast<__half2*>(&c8);
    __half2 r = __hsub2(a, b);
    return *reinterpret_cast<uint32_t*>(&r);
}

// parallel dtype sniff (was 1-thread serial = ~40us!)
__global__ void sniff_vals(const unsigned short* __restrict__ p) {
    __shared__ int a16, abf;
    const int t = threadIdx.x;   // 128 threads
    if (t == 0) { a16 = 1; abf = 1; }
    __syncthreads();
    unsigned short u = p[t];
    float h = __half2float(__ushort_as_half(u));
    float b = __uint_as_float(((uint32_t)u) << 16);
    if (!(fabsf(h) < 0.5f)) atomicAnd(&a16, 0);
    if (!(fabsf(b) < 0.5f)) atomicAnd(&abf, 0);
    __syncthreads();
    if (t == 0) g_mode = a16 ? 0 : (abf ? 1 : 2);
}

__global__ void convert_x(const float* __restrict__ x) {
    int i = blockIdx.x * blockDim.x + threadIdx.x;
    if (i < MM * II / 4) {
        float4 v = reinterpret_cast<const float4*>(x)[i];
        reinterpret_cast<__half2*>(g_xh)[i * 2 + 0] = __floats2half2_rn(v.x, v.y);
        reinterpret_cast<__half2*>(g_xh)[i * 2 + 1] = __floats2half2_rn(v.z, v.w);
    }
}

__global__ void residual_prep(const void* __restrict__ vals, const int* __restrict__ idx,
                              const int* __restrict__ ptr, const float* __restrict__ scales,
                              const float* __restrict__ alphap) {
    __shared__ int cnt[NBUCKET], run[NBUCKET], pref[NBUCKET + 1];
    const int o = blockIdx.x, t = threadIdx.x;
    const int s = ptr[o], e = ptr[o + 1], n = e - s;
    const int mode = g_mode;
    cnt[t] = 0; run[t] = 0;
    __syncthreads();
    for (int j = t; j < n; j += 256) atomicAdd(&cnt[idx[s + j] >> 5], 1);
    __syncthreads();
    if (t == 0) { int a = 0; for (int c = 0; c < NBUCKET; c++) { pref[c] = a; a += cnt[c]; } pref[NBUCKET] = a; }
    __syncthreads();
    g_roff[o * (NBUCKET + 1) + t] = s + pref[t];
    if (t == 0) g_roff[o * (NBUCKET + 1) + NBUCKET] = s + pref[NBUCKET];
    const float inv = alphap[0] / scales[o];
    for (int j = t; j < n; j += 256) {
        const int k = idx[s + j];
        const int pos = s + pref[k >> 5] + atomicAdd(&run[k >> 5], 1);
        float v;
        if (mode == 0)      v = __half2float(reinterpret_cast<const __half*>(vals)[s + j]);
        else if (mode == 1) v = __uint_as_float(((uint32_t)reinterpret_cast<const unsigned short*>(vals)[s + j]) << 16);
        else                v = reinterpret_cast<const float*>(vals)[s + j];
        g_rk[pos] = (unsigned short)k;
        g_rv[pos] = __float2half_rn(v * inv);
    }
}

// ---- fused dequant GEMM: out[256,8192] = x @ W^T ----
// CTA 128m x 128o, K chunks 128, 3 stages, 512 threads:
// warps 0-7 consumers (warp tile 64x32, 2m x 4n), warps 8-15 producers.
// named barriers: full[s] = 1+s, empty[s] = 4+s, count 512.

// producer A: 2048 16B vecs, 256 prod threads, 8 each
__device__ __forceinline__ void cpa_A(uint32_t Ab, int m_base, int k0, int pt) {
#pragma unroll
    for (int r = 0; r < 8; r++) {
        const int u = pt + r * 256, row = u >> 4, seg = u & 15;
        const __half* src = g_xh + (size_t)(m_base + row) * II + k0 + seg * 8;
        uint32_t off = ((uint32_t)(seg >> 3) << 14) + (uint32_t)(row * 128 + (seg & 7) * 16);
        asm volatile("cp.async.cg.shared.global [%0], [%1], 16;" :: "r"(Ab + sw(off)), "l"(src));
    }
    asm volatile("cp.async.commit_group;" ::: "memory");
}
// producer B: thread pt owns (row = pt>>1, 64-k half = pt&1) -> 8 consecutive uint4
__device__ __forceinline__ void ldg_B(const int* __restrict__ packed, int o_base, int k0, int pt, uint4* pk) {
    const int row = pt >> 1, h = pt & 1;
    const uint4* src = reinterpret_cast<const uint4*>(
        packed + (size_t)(o_base + row) * (II / 2) + (k0 >> 1) + h * 32);
#pragma unroll
    for (int j = 0; j < 8; j++) pk[j] = src[j];
}
__device__ __forceinline__ void sts_fold_B(uint32_t Bb, const uint4* pk, int o_base, int k0, int pt) {
    const int row = pt >> 1, h = pt & 1;
    const uint32_t hb = ((uint32_t)h << 14) + (uint32_t)(row * 128);
#pragma unroll
    for (int j = 0; j < 8; j++) {
        uint32_t ad = Bb + sw(hb + j * 16);
        asm volatile("st.shared.v4.b32 [%0], {%1,%2,%3,%4};"
                     :: "r"(ad), "r"(dq(pk[j].x)), "r"(dq(pk[j].y)),
                        "r"(dq(pk[j].z)), "r"(dq(pk[j].w)) : "memory");
    }
    // residual fold: same thread owns this (row, 64-k half): buckets 2h, 2h+1
    const int o = o_base + row;
    const int kb = k0 + h * 64;
#pragma unroll
    for (int bb = 0; bb < 2; bb++) {
        const int b = (k0 >> 5) + 2 * h + bb;
        const int s0 = g_roff[o * (NBUCKET + 1) + b];
        const int s1 = g_roff[o * (NBUCKET + 1) + b + 1];
        for (int j = s0; j < s1; j++) {
            const int kl = (int)g_rk[j] - kb;
            uint32_t ad = Bb + sw(hb + (uint32_t)(kl * 2));
            unsigned short u16;
            asm volatile("ld.shared.b16 %0, [%1];" : "=h"(u16) : "r"(ad));
            __half v = __hadd(__ushort_as_half(u16), g_rv[j]);
            u16 = __half_as_ushort(v);
            asm volatile("st.shared.b16 [%0], %1;" :: "r"(ad), "h"(u16) : "memory");
        }
    }
}

#define PROD_STEP(f, PKC, PKN) { \
    const int s_ = (f) % 3; \
    if ((f) >= STAGES) \
        asm volatile("bar.sync %0, %1;" :: "r"(4 + s_), "r"(512) : "memory"); \
    const uint32_t base_ = sb + (uint32_t)s_ * STAGE_BYTES; \
    cpa_A(base_, m_base, (f) * 128, pt); \
    sts_fold_B(base_ + 32768u, PKC, o_base, (f) * 128, pt); \
    if ((f) + 1 < NITER) ldg_B(packed, o_base, ((f) + 1) * 128, pt, PKN); \
    asm volatile("cp.async.wait_group 0;" ::: "memory"); \
    asm volatile("bar.arrive %0, %1;" :: "r"(1 + s_), "r"(512) : "memory"); \
}

__global__ void __launch_bounds__(512, 1)
gemm_kernel(const int* __restrict__ packed, const float* __restrict__ scales, float* __restrict__ out) {
    extern __shared__ char smem[];
    const uint32_t sb = smem_u32(smem);
    const int tid = threadIdx.x, wid = tid >> 5, lane = tid & 31;
    const int n_idx = blockIdx.x >> 1, m_idx = blockIdx.x & 1;
    const int o_base = n_idx * 128, m_base = m_idx * 128;

    if (wid < 8) {
        // ---------------- consumer: warp tile 64x32, 2m x 4n grid ----------------
        const int wm = wid >> 2, wn = wid & 3;
        float c[4][4][4];
#pragma unroll
        for (int mt = 0; mt < 4; mt++)
#pragma unroll
            for (int nt = 0; nt < 4; nt++)
#pragma unroll
                for (int q = 0; q < 4; q++) c[mt][nt][q] = 0.f;

        for (int ch = 0; ch < NITER; ch++) {
            const int s_ = ch % 3;
            const uint32_t cur = sb + (uint32_t)s_ * STAGE_BYTES;
            asm volatile("bar.sync %0, %1;" :: "r"(1 + s_), "r"(512) : "memory");
#pragma unroll
            for (int kk = 0; kk < 8; kk++) {
                const uint32_t khoff = ((uint32_t)(kk >> 2) << 14);
                const int kkl = kk & 3;
                uint32_t a[4][4], b[4][2];
#pragma unroll
                for (int mt = 0; mt < 4; mt++) {
                    const int row = wm * 64 + mt * 16 + (lane & 15);
                    uint32_t ad = cur + sw(khoff + (uint32_t)(row * 128 + kkl * 32 + (lane >> 4) * 16));
                    asm volatile("ldmatrix.sync.aligned.m8n8.x4.shared.b16 {%0,%1,%2,%3}, [%4];"
                                 : "=r"(a[mt][0]), "=r"(a[mt][1]), "=r"(a[mt][2]), "=r"(a[mt][3]) : "r"(ad));
                }
#pragma unroll
                for (int ntp = 0; ntp < 2; ntp++) {
                    const int row = wn * 32 + ntp * 16 + ((lane >> 4) & 1) * 8 + (lane & 7);
                    uint32_t ad = cur + 32768u + sw(khoff + (uint32_t)(row * 128 + kkl * 32 + ((lane >> 3) & 1) * 16));
                    asm volatile("ldmatrix.sync.aligned.m8n8.x4.shared.b16 {%0,%1,%2,%3}, [%4];"
                                 : "=r"(b[2 * ntp][0]), "=r"(b[2 * ntp][1]),
                                   "=r"(b[2 * ntp + 1][0]), "=r"(b[2 * ntp + 1][1]) : "r"(ad));
                }
#pragma unroll
                for (int mt = 0; mt < 4; mt++)
#pragma unroll
                    for (int nt = 0; nt < 4; nt++)
                        asm volatile("mma.sync.aligned.m16n8k16.row.col.f32.f16.f16.f32 "
                                     "{%0,%1,%2,%3}, {%4,%5,%6,%7}, {%8,%9}, {%0,%1,%2,%3};"
                                     : "+f"(c[mt][nt][0]), "+f"(c[mt][nt][1]), "+f"(c[mt][nt][2]), "+f"(c[mt][nt][3])
                                     : "r"(a[mt][0]), "r"(a[mt][1]), "r"(a[mt][2]), "r"(a[mt][3]),
                                       "r"(b[nt][0]), "r"(b[nt][1]));
            }
            asm volatile("bar.arrive %0, %1;" :: "r"(4 + s_), "r"(512) : "memory");
        }

        // epilogue: per-o scale in fp32, direct float2 stores
#pragma unroll
        for (int mt = 0; mt < 4; mt++) {
            const int m0 = m_base + wm * 64 + mt * 16 + (lane >> 2);
#pragma unroll
            for (int nt = 0; nt < 4; nt++) {
                const int o = o_base + wn * 32 + nt * 8 + (lane & 3) * 2;
                const float2 s = *reinterpret_cast<const float2*>(scales + o);
                float2 r0, r1;
                r0.x = c[mt][nt][0] * s.x; r0.y = c[mt][nt][1] * s.y;
                r1.x = c[mt][nt][2] * s.x; r1.y = c[mt][nt][3] * s.y;
                *reinterpret_cast<float2*>(out + (size_t)m0 * OO + o) = r0;
                *reinterpret_cast<float2*>(out + (size_t)(m0 + 8) * OO + o) = r1;
            }
        }
    } else {
        // ---------------- producer: 256 threads ----------------
        const int pt = tid - 256;
        uint4 pk0[8], pk1[8];
        ldg_B(packed, o_base, 0, pt, pk0);
        for (int f = 0; f < NITER; f += 2) {
            PROD_STEP(f,     pk0, pk1);
            PROD_STEP(f + 1, pk1, pk0);
        }
    }
}

extern "C" void kernel_launch(void* const* d_in, const int* in_sizes, int n_in,
                              void* d_out, int out_size) {
    const float* x      = (const float*)d_in[0];
    const int*   packed = (const int*)d_in[1];
    const float* scales = (const float*)d_in[2];
    const void*  vals   = (const void*)d_in[3];
    const int*   idx    = (const int*)d_in[4];
    const int*   ptr    = (const int*)d_in[5];
    const float* alpha  = (const float*)d_in[6];
    float* out = (float*)d_out;

    cudaFuncSetAttribute(gemm_kernel, cudaFuncAttributeMaxDynamicSharedMemorySize, SMEM_BYTES);
    sniff_vals<<<1, 128>>>((const unsigned short*)vals);
    convert_x<<<2048, 256>>>(x);
    residual_prep<<<OO, 256>>>(vals, idx, ptr, scales, alpha);
    gemm_kernel<<<128, 512, SMEM_BYTES>>>(packed, scales, out);
}

// round 12
// speedup vs baseline: 1.3194x; 1.3194x over previous
#include <cuda_runtime.h>
#include <cuda_fp16.h>
#include <cstdint>

#define MM 256
#define OO 8192
#define II 8192
#define NNZ_TOTAL 3350528
#define NBUCKET 256          // 32-wide k buckets
#define NITER 64             // II / 128
#define STAGES 3
#define STAGE_BYTES 65536    // A 32KB + B 32KB
#define SMEM_BYTES (STAGES * STAGE_BYTES)   // 196608

__device__ __half         g_xh[MM * II];
__device__ unsigned short g_rk[NNZ_TOTAL];
__device__ __half         g_rv[NNZ_TOTAL];
__device__ int            g_roff[OO * (NBUCKET + 1)];
__device__ int            g_mode;   // 0=f16, 1=bf16, 2=f32

__device__ __forceinline__ uint32_t smem_u32(const void* p) {
    uint32_t a;
    asm("{ .reg .u64 t; cvta.to.shared.u64 t, %1; cvt.u32.u64 %0, t; }" : "=r"(a) : "l"(p));
    return a;
}
__device__ __forceinline__ uint32_t sw(uint32_t off) { return off ^ ((off >> 3) & 0x70u); }
// one packed int32 holds ONE byte: low nibble -> even k, high nibble -> odd k; (value-8) exact in f16
__device__ __forceinline__ uint32_t dq(uint32_t v) {
    uint32_t h = 0x64006400u | (v & 0xFu) | ((v << 12) & 0x000F0000u);
    __half2 a = *reinterpret_cast<__half2*>(&h);
    uint32_t c8 = 0x64086408u;
    __half2 b = *reinterpret_cast<__half2*>(&c8);
    __half2 r = __hsub2(a, b);
    return *reinterpret_cast<uint32_t*>(&r);
}

// parallel dtype sniff (1-thread serial version cost ~40us)
__global__ void sniff_vals(const unsigned short* __restrict__ p) {
    __shared__ int a16, abf;
    const int t = threadIdx.x;   // 128 threads
    if (t == 0) { a16 = 1; abf = 1; }
    __syncthreads();
    unsigned short u = p[t];
    float h = __half2float(__ushort_as_half(u));
    float b = __uint_as_float(((uint32_t)u) << 16);
    if (!(fabsf(h) < 0.5f)) atomicAnd(&a16, 0);
    if (!(fabsf(b) < 0.5f)) atomicAnd(&abf, 0);
    __syncthreads();
    if (t == 0) g_mode = a16 ? 0 : (abf ? 1 : 2);
}

// fused prep: blocks [0,2048) convert x fp32->fp16; blocks [2048,10240) sort residuals
__global__ void prep_kernel(const float* __restrict__ x,
                            const void* __restrict__ vals, const int* __restrict__ idx,
                            const int* __restrict__ ptr, const float* __restrict__ scales,
                            const float* __restrict__ alphap) {
    if (blockIdx.x < 2048) {
        int i = blockIdx.x * 256 + threadIdx.x;
        float4 v = reinterpret_cast<const float4*>(x)[i];
        reinterpret_cast<__half2*>(g_xh)[i * 2 + 0] = __floats2half2_rn(v.x, v.y);
        reinterpret_cast<__half2*>(g_xh)[i * 2 + 1] = __floats2half2_rn(v.z, v.w);
        return;
    }
    __shared__ int cnt[NBUCKET], run[NBUCKET], pref[NBUCKET + 1];
    const int o = blockIdx.x - 2048, t = threadIdx.x;
    const int s = ptr[o], e = ptr[o + 1], n = e - s;
    const int mode = g_mode;
    cnt[t] = 0; run[t] = 0;
    __syncthreads();
    for (int j = t; j < n; j += 256) atomicAdd(&cnt[idx[s + j] >> 5], 1);
    __syncthreads();
    if (t == 0) { int a = 0; for (int c = 0; c < NBUCKET; c++) { pref[c] = a; a += cnt[c]; } pref[NBUCKET] = a; }
    __syncthreads();
    g_roff[o * (NBUCKET + 1) + t] = s + pref[t];
    if (t == 0) g_roff[o * (NBUCKET + 1) + NBUCKET] = s + pref[NBUCKET];
    const float inv = alphap[0] / scales[o];
    for (int j = t; j < n; j += 256) {
        const int k = idx[s + j];
        const int pos = s + pref[k >> 5] + atomicAdd(&run[k >> 5], 1);
        float v;
        if (mode == 0)      v = __half2float(reinterpret_cast<const __half*>(vals)[s + j]);
        else if (mode == 1) v = __uint_as_float(((uint32_t)reinterpret_cast<const unsigned short*>(vals)[s + j]) << 16);
        else                v = reinterpret_cast<const float*>(vals)[s + j];
        g_rk[pos] = (unsigned short)k;
        g_rv[pos] = __float2half_rn(v * inv);
    }
}

// ---- fused dequant GEMM: out[256,8192] = x @ W^T ----
// CTA tile 128(m) x 128(o), K chunks of 128, 3-stage pipeline, 512 threads,
// 16 warps, warp tile 32x32 (4x4 grid).  [R8 champion structure]
__device__ __forceinline__ void cpa_A(uint32_t Ab, int m_base, int k0, int tid) {
#pragma unroll
    for (int r = 0; r < 4; r++) {
        const int u = tid + r * 512, row = u >> 4, seg = u & 15;
        const __half* src = g_xh + (size_t)(m_base + row) * II + k0 + seg * 8;
        uint32_t off = ((uint32_t)(seg >> 3) << 14) + (uint32_t)(row * 128 + (seg & 7) * 16);
        asm volatile("cp.async.cg.shared.global [%0], [%1], 16;" :: "r"(Ab + sw(off)), "l"(src));
    }
    asm volatile("cp.async.commit_group;" ::: "memory");
}
__device__ __forceinline__ void ldg_B(const int* __restrict__ packed, int o_base, int k0, int tid, uint4* pk) {
    const int row = tid >> 2, seg = tid & 3;
    const uint4* src = reinterpret_cast<const uint4*>(
        packed + (size_t)(o_base + row) * (II / 2) + (k0 >> 1) + seg * 16);
#pragma unroll
    for (int j = 0; j < 4; j++) pk[j] = src[j];
}
__device__ __forceinline__ void sts_fold_B(uint32_t Bb, const uint4* pk, int o_base, int k0, int tid) {
    const int row = tid >> 2, seg = tid & 3;
    const uint32_t hb = ((uint32_t)(seg >> 1) << 14) + (uint32_t)(row * 128 + (seg & 1) * 64);
#pragma unroll
    for (int j = 0; j < 4; j++) {
        uint32_t ad = Bb + sw(hb + j * 16);
        asm volatile("st.shared.v4.b32 [%0], {%1,%2,%3,%4};"
                     :: "r"(ad), "r"(dq(pk[j].x)), "r"(dq(pk[j].y)), "r"(dq(pk[j].z)), "r"(dq(pk[j].w)) : "memory");
    }
    // residual fold: same thread owns this (row, 32-k) window -> program-order safe
    const int o = o_base + row;
    const int b = (k0 >> 5) + seg;
    const int s0 = g_roff[o * (NBUCKET + 1) + b];
    const int s1 = g_roff[o * (NBUCKET + 1) + b + 1];
    const int kb = k0 + seg * 32;
    for (int j = s0; j < s1; j++) {
        const int kl = (int)g_rk[j] - kb;
        uint32_t ad = Bb + sw(hb + (uint32_t)(kl * 2));
        unsigned short u16;
        asm volatile("ld.shared.b16 %0, [%1];" : "=h"(u16) : "r"(ad));
        __half v = __hadd(__ushort_as_half(u16), g_rv[j]);
        u16 = __half_as_ushort(v);
        asm volatile("st.shared.b16 [%0], %1;" :: "r"(ad), "h"(u16) : "memory");
    }
}

__global__ void __launch_bounds__(512, 1)
gemm_kernel(const int* __restrict__ packed, const float* __restrict__ scales, float* __restrict__ out) {
    extern __shared__ char smem[];
    const uint32_t sb = smem_u32(smem);
    const int tid = threadIdx.x, wid = tid >> 5, lane = tid & 31;
    const int wm = wid >> 2, wn = wid & 3;                 // 4x4 warps, warp tile 32x32
    const int n_idx = blockIdx.x >> 1, m_idx = blockIdx.x & 1;
    const int o_base = n_idx * 128, m_base = m_idx * 128;

    float c[2][4][4];
#pragma unroll
    for (int mt = 0; mt < 2; mt++)
#pragma unroll
        for (int nt = 0; nt < 4; nt++)
#pragma unroll
            for (int q = 0; q < 4; q++) c[mt][nt][q] = 0.f;

    // prologue: fill stages 0,1
#pragma unroll
    for (int s = 0; s < STAGES - 1; s++) {
        const uint32_t base = sb + s * STAGE_BYTES;
        cpa_A(base, m_base, s * 128, tid);
        uint4 pk[4];
        ldg_B(packed, o_base, s * 128, tid, pk);
        sts_fold_B(base + 32768u, pk, o_base, s * 128, tid);
    }

    for (int ch = 0; ch < NITER; ch++) {
        const uint32_t cur = sb + (uint32_t)(ch % STAGES) * STAGE_BYTES;
        uint4 pk[4];
        const bool produce = (ch + STAGES - 1) < NITER;
        const int pch = ch + STAGES - 1;
        const uint32_t pbase = sb + (uint32_t)(pch % STAGES) * STAGE_BYTES;

        // B LDGs issued BEFORE wait+barrier: register-only, gains the convoy time as extra DRAM cover
        if (produce) ldg_B(packed, o_base, pch * 128, tid, pk);

        if (ch == NITER - 1) asm volatile("cp.async.wait_group 0;" ::: "memory");
        else                 asm volatile("cp.async.wait_group 1;" ::: "memory");
        __syncthreads();   // stage ch visible; all warps done with stage ch-1 -> its buffer reusable

        if (produce) cpa_A(pbase, m_base, pch * 128, tid);   // writes stage (ch-1)%3: safe only after bar

#pragma unroll
        for (int kk = 0; kk < 8; kk++) {
            const uint32_t khoff = ((uint32_t)(kk >> 2) << 14);
            const int kkl = kk & 3;
            uint32_t a[2][4], b[4][2];
#pragma unroll
            for (int mt = 0; mt < 2; mt++) {
                const int row = wm * 32 + mt * 16 + (lane & 15);
                uint32_t ad = cur + sw(khoff + (uint32_t)(row * 128 + kkl * 32 + (lane >> 4) * 16));
                asm volatile("ldmatrix.sync.aligned.m8n8.x4.shared.b16 {%0,%1,%2,%3}, [%4];"
                             : "=r"(a[mt][0]), "=r"(a[mt][1]), "=r"(a[mt][2]), "=r"(a[mt][3]) : "r"(ad));
            }
#pragma unroll
            for (int ntp = 0; ntp < 2; ntp++) {
                const int row = wn * 32 + ntp * 16 + ((lane >> 4) & 1) * 8 + (lane & 7);
                uint32_t ad = cur + 32768u + sw(khoff + (uint32_t)(row * 128 + kkl * 32 + ((lane >> 3) & 1) * 16));
                asm volatile("ldmatrix.sync.aligned.m8n8.x4.shared.b16 {%0,%1,%2,%3}, [%4];"
                             : "=r"(b[2 * ntp][0]), "=r"(b[2 * ntp][1]),
                               "=r"(b[2 * ntp + 1][0]), "=r"(b[2 * ntp + 1][1]) : "r"(ad));
            }
#pragma unroll
            for (int mt = 0; mt < 2; mt++)
#pragma unroll
                for (int nt = 0; nt < 4; nt++)
                    asm volatile("mma.sync.aligned.m16n8k16.row.col.f32.f16.f16.f32 "
                                 "{%0,%1,%2,%3}, {%4,%5,%6,%7}, {%8,%9}, {%0,%1,%2,%3};"
                                 : "+f"(c[mt][nt][0]), "+f"(c[mt][nt][1]), "+f"(c[mt][nt][2]), "+f"(c[mt][nt][3])
                                 : "r"(a[mt][0]), "r"(a[mt][1]), "r"(a[mt][2]), "r"(a[mt][3]),
                                   "r"(b[nt][0]), "r"(b[nt][1]));
        }

        if (produce)
            sts_fold_B(pbase + 32768u, pk, o_base, pch * 128, tid);  // own stores; visible via later barriers
    }

    // epilogue: per-o scale in fp32, direct float2 stores
#pragma unroll
    for (int mt = 0; mt < 2; mt++) {
        const int m0 = m_base + wm * 32 + mt * 16 + (lane >> 2);
#pragma unroll
        for (int nt = 0; nt < 4; nt++) {
            const int o = o_base + wn * 32 + nt * 8 + (lane & 3) * 2;
            const float2 s = *reinterpret_cast<const float2*>(scales + o);
            float2 r0, r1;
            r0.x = c[mt][nt][0] * s.x; r0.y = c[mt][nt][1] * s.y;
            r1.x = c[mt][nt][2] * s.x; r1.y = c[mt][nt][3] * s.y;
            *reinterpret_cast<float2*>(out + (size_t)m0 * OO + o) = r0;
            *reinterpret_cast<float2*>(out + (size_t)(m0 + 8) * OO + o) = r1;
        }
    }
}

extern "C" void kernel_launch(void* const* d_in, const int* in_sizes, int n_in,
                              void* d_out, int out_size) {
    const float* x      = (const float*)d_in[0];
    const int*   packed = (const int*)d_in[1];
    const float* scales = (const float*)d_in[2];
    const void*  vals   = (const void*)d_in[3];
    const int*   idx    = (const int*)d_in[4];
    const int*   ptr    = (const int*)d_in[5];
    const float* alpha  = (const float*)d_in[6];
    float* out = (float*)d_out;

    cudaFuncSetAttribute(gemm_kernel, cudaFuncAttributeMaxDynamicSharedMemorySize, SMEM_BYTES);
    sniff_vals<<<1, 128>>>((const unsigned short*)vals);
    prep_kernel<<<2048 + OO, 256>>>(x, vals, idx, ptr, scales, alpha);
    gemm_kernel<<<128, 512, SMEM_BYTES>>>(packed, scales, out);
}

// round 13
// speedup vs baseline: 1.3882x; 1.0521x over previous
#include <cuda_runtime.h>
#include <cuda_fp16.h>
#include <cstdint>

#define MM 256
#define OO 8192
#define II 8192
#define NNZ_TOTAL 3350528
#define NBUCKET 256          // 32-wide k buckets
#define NITER 64             // II / 128
#define STAGES 2
#define A_BYTES 65536        // 256 rows x 128k fp16 (two 32KB k-halves)
#define B_BYTES 16384        // 64 rows x 128k fp16 (two 8KB k-halves)
#define STAGE_BYTES (A_BYTES + B_BYTES)     // 81920
#define SMEM_BYTES (STAGES * STAGE_BYTES)   // 163840

__device__ __half         g_xh[MM * II];
__device__ unsigned short g_rk[NNZ_TOTAL];
__device__ __half         g_rv[NNZ_TOTAL];
__device__ int            g_roff[OO * (NBUCKET + 1)];
__device__ int            g_mode;   // 0=f16, 1=bf16, 2=f32

__device__ __forceinline__ uint32_t smem_u32(const void* p) {
    uint32_t a;
    asm("{ .reg .u64 t; cvta.to.shared.u64 t, %1; cvt.u32.u64 %0, t; }" : "=r"(a) : "l"(p));
    return a;
}
__device__ __forceinline__ uint32_t sw(uint32_t off) { return off ^ ((off >> 3) & 0x70u); }
// one packed int32 holds ONE byte: low nibble -> even k, high nibble -> odd k; (value-8) exact in f16
__device__ __forceinline__ uint32_t dq(uint32_t v) {
    uint32_t h = 0x64006400u | (v & 0xFu) | ((v << 12) & 0x000F0000u);
    __half2 a = *reinterpret_cast<__half2*>(&h);
    uint32_t c8 = 0x64086408u;
    __half2 b = *reinterpret_cast<__half2*>(&c8);
    __half2 r = __hsub2(a, b);
    return *reinterpret_cast<uint32_t*>(&r);
}

// parallel dtype sniff
__global__ void sniff_vals(const unsigned short* __restrict__ p) {
    __shared__ int a16, abf;
    const int t = threadIdx.x;   // 128 threads
    if (t == 0) { a16 = 1; abf = 1; }
    __syncthreads();
    unsigned short u = p[t];
    float h = __half2float(__ushort_as_half(u));
    float b = __uint_as_float(((uint32_t)u) << 16);
    if (!(fabsf(h) < 0.5f)) atomicAnd(&a16, 0);
    if (!(fabsf(b) < 0.5f)) atomicAnd(&abf, 0);
    __syncthreads();
    if (t == 0) g_mode = a16 ? 0 : (abf ? 1 : 2);
}

// fused prep: blocks [0,2048) convert x fp32->fp16; blocks [2048,10240) sort residuals
__global__ void prep_kernel(const float* __restrict__ x,
                            const void* __restrict__ vals, const int* __restrict__ idx,
                            const int* __restrict__ ptr, const float* __restrict__ scales,
                            const float* __restrict__ alphap) {
    if (blockIdx.x < 2048) {
        int i = blockIdx.x * 256 + threadIdx.x;
        float4 v = reinterpret_cast<const float4*>(x)[i];
        reinterpret_cast<__half2*>(g_xh)[i * 2 + 0] = __floats2half2_rn(v.x, v.y);
        reinterpret_cast<__half2*>(g_xh)[i * 2 + 1] = __floats2half2_rn(v.z, v.w);
        return;
    }
    __shared__ int cnt[NBUCKET], run[NBUCKET], pref[NBUCKET + 1];
    const int o = blockIdx.x - 2048, t = threadIdx.x;
    const int s = ptr[o], e = ptr[o + 1], n = e - s;
    const int mode = g_mode;
    cnt[t] = 0; run[t] = 0;
    __syncthreads();
    for (int j = t; j < n; j += 256) atomicAdd(&cnt[idx[s + j] >> 5], 1);
    __syncthreads();
    if (t == 0) { int a = 0; for (int c = 0; c < NBUCKET; c++) { pref[c] = a; a += cnt[c]; } pref[NBUCKET] = a; }
    __syncthreads();
    g_roff[o * (NBUCKET + 1) + t] = s + pref[t];
    if (t == 0) g_roff[o * (NBUCKET + 1) + NBUCKET] = s + pref[NBUCKET];
    const float inv = alphap[0] / scales[o];
    for (int j = t; j < n; j += 256) {
        const int k = idx[s + j];
        const int pos = s + pref[k >> 5] + atomicAdd(&run[k >> 5], 1);
        float v;
        if (mode == 0)      v = __half2float(reinterpret_cast<const __half*>(vals)[s + j]);
        else if (mode == 1) v = __uint_as_float(((uint32_t)reinterpret_cast<const unsigned short*>(vals)[s + j]) << 16);
        else                v = reinterpret_cast<const float*>(vals)[s + j];
        g_rk[pos] = (unsigned short)k;
        g_rv[pos] = __float2half_rn(v * inv);
    }
}

// ---- fused dequant GEMM: out[256,8192] = x @ W^T ----
// CTA tile m=256 (ALL M) x o=64: each W byte dequantized exactly ONCE chip-wide.
// K chunks 128, 2 stages, 512 threads, warp tile 32x32 (8m x 2n grid).
// A: 4096 16B vecs / 512 threads = 8 each
__device__ __forceinline__ void cpa_A(uint32_t Ab, int k0, int tid) {
#pragma unroll
    for (int r = 0; r < 8; r++) {
        const int u = tid + r * 512, row = u >> 4, seg = u & 15;
        const __half* src = g_xh + (size_t)row * II + k0 + seg * 8;
        uint32_t off = ((uint32_t)(seg >> 3) << 15) + (uint32_t)(row * 128 + (seg & 7) * 16);
        asm volatile("cp.async.cg.shared.global [%0], [%1], 16;" :: "r"(Ab + sw(off)), "l"(src));
    }
    asm volatile("cp.async.commit_group;" ::: "memory");
}
// B: threads 0..255 own (row = tid>>2 in 0..63, 32-k window = tid&3)
__device__ __forceinline__ void ldg_B(const int* __restrict__ packed, int o_base, int k0, int tid, uint4* pk) {
    if (tid >= 256) return;
    const int row = tid >> 2, seg = tid & 3;
    const uint4* src = reinterpret_cast<const uint4*>(
        packed + (size_t)(o_base + row) * (II / 2) + (k0 >> 1) + seg * 16);
#pragma unroll
    for (int j = 0; j < 4; j++) pk[j] = src[j];
}
__device__ __forceinline__ void sts_fold_B(uint32_t Bb, const uint4* pk, int o_base, int k0, int tid) {
    if (tid >= 256) return;
    const int row = tid >> 2, seg = tid & 3;
    const uint32_t hb = ((uint32_t)(seg >> 1) << 13) + (uint32_t)(row * 128 + (seg & 1) * 64);
#pragma unroll
    for (int j = 0; j < 4; j++) {
        uint32_t ad = Bb + sw(hb + j * 16);
        asm volatile("st.shared.v4.b32 [%0], {%1,%2,%3,%4};"
                     :: "r"(ad), "r"(dq(pk[j].x)), "r"(dq(pk[j].y)), "r"(dq(pk[j].z)), "r"(dq(pk[j].w)) : "memory");
    }
    // residual fold: same thread owns this (row, 32-k) window -> program-order safe
    const int o = o_base + row;
    const int b = (k0 >> 5) + seg;
    const int s0 = g_roff[o * (NBUCKET + 1) + b];
    const int s1 = g_roff[o * (NBUCKET + 1) + b + 1];
    const int kb = k0 + seg * 32;
    for (int j = s0; j < s1; j++) {
        const int kl = (int)g_rk[j] - kb;
        uint32_t ad = Bb + sw(hb + (uint32_t)(kl * 2));
        unsigned short u16;
        asm volatile("ld.shared.b16 %0, [%1];" : "=h"(u16) : "r"(ad));
        __half v = __hadd(__ushort_as_half(u16), g_rv[j]);
        u16 = __half_as_ushort(v);
        asm volatile("st.shared.b16 [%0], %1;" :: "r"(ad), "h"(u16) : "memory");
    }
}

__global__ void __launch_bounds__(512, 1)
gemm_kernel(const int* __restrict__ packed, const float* __restrict__ scales, float* __restrict__ out) {
    extern __shared__ char smem[];
    const uint32_t sb = smem_u32(smem);
    const int tid = threadIdx.x, wid = tid >> 5, lane = tid & 31;
    const int wm = wid >> 1, wn = wid & 1;                 // 8m x 2n warps, warp tile 32x32
    const int o_base = blockIdx.x * 64;

    float c[2][4][4];
#pragma unroll
    for (int mt = 0; mt < 2; mt++)
#pragma unroll
        for (int nt = 0; nt < 4; nt++)
#pragma unroll
            for (int q = 0; q < 4; q++) c[mt][nt][q] = 0.f;

    // prologue: fill stage 0
    {
        cpa_A(sb, 0, tid);                                  // commits g0
        uint4 pk[4];
        ldg_B(packed, o_base, 0, tid, pk);
        sts_fold_B(sb + A_BYTES, pk, o_base, 0, tid);
    }

    for (int ch = 0; ch < NITER; ch++) {
        const uint32_t cur = sb + (uint32_t)(ch & 1) * STAGE_BYTES;
        uint4 pk[4];
        const bool produce = (ch + 1) < NITER;
        const int pch = ch + 1;
        const uint32_t pbase = sb + (uint32_t)(pch & 1) * STAGE_BYTES;

        // pre-barrier: B LDGs for next chunk (register-only), gains convoy time as DRAM cover
        if (produce) ldg_B(packed, o_base, pch * 128, tid, pk);

        asm volatile("cp.async.wait_group 0;" ::: "memory");   // stage ch's A complete
        __syncthreads();   // stage ch visible to all; all warps done with stage ch-1 -> reusable

        if (produce) cpa_A(pbase, pch * 128, tid);             // fills other stage during compute

#pragma unroll
        for (int kk = 0; kk < 8; kk++) {
            const uint32_t akh = ((uint32_t)(kk >> 2) << 15);
            const uint32_t bkh = ((uint32_t)(kk >> 2) << 13);
            const int kkl = kk & 3;
            uint32_t a[2][4], b[4][2];
#pragma unroll
            for (int mt = 0; mt < 2; mt++) {
                const int row = wm * 32 + mt * 16 + (lane & 15);
                uint32_t ad = cur + sw(akh + (uint32_t)(row * 128 + kkl * 32 + (lane >> 4) * 16));
                asm volatile("ldmatrix.sync.aligned.m8n8.x4.shared.b16 {%0,%1,%2,%3}, [%4];"
                             : "=r"(a[mt][0]), "=r"(a[mt][1]), "=r"(a[mt][2]), "=r"(a[mt][3]) : "r"(ad));
            }
#pragma unroll
            for (int ntp = 0; ntp < 2; ntp++) {
                const int row = wn * 32 + ntp * 16 + ((lane >> 4) & 1) * 8 + (lane & 7);
                uint32_t ad = cur + A_BYTES + sw(bkh + (uint32_t)(row * 128 + kkl * 32 + ((lane >> 3) & 1) * 16));
                asm volatile("ldmatrix.sync.aligned.m8n8.x4.shared.b16 {%0,%1,%2,%3}, [%4];"
                             : "=r"(b[2 * ntp][0]), "=r"(b[2 * ntp][1]),
                               "=r"(b[2 * ntp + 1][0]), "=r"(b[2 * ntp + 1][1]) : "r"(ad));
            }
#pragma unroll
            for (int mt = 0; mt < 2; mt++)
#pragma unroll
                for (int nt = 0; nt < 4; nt++)
                    asm volatile("mma.sync.aligned.m16n8k16.row.col.f32.f16.f16.f32 "
                                 "{%0,%1,%2,%3}, {%4,%5,%6,%7}, {%8,%9}, {%0,%1,%2,%3};"
                                 : "+f"(c[mt][nt][0]), "+f"(c[mt][nt][1]), "+f"(c[mt][nt][2]), "+f"(c[mt][nt][3])
                                 : "r"(a[mt][0]), "r"(a[mt][1]), "r"(a[mt][2]), "r"(a[mt][3]),
                                   "r"(b[nt][0]), "r"(b[nt][1]));
        }

        if (produce)
            sts_fold_B(pbase + A_BYTES, pk, o_base, pch * 128, tid);  // own stores; visible via next bar
    }

    // epilogue: per-o scale in fp32, direct float2 stores
#pragma unroll
    for (int mt = 0; mt < 2; mt++) {
        const int m0 = wm * 32 + mt * 16 + (lane >> 2);
#pragma unroll
        for (int nt = 0; nt < 4; nt++) {
            const int o = o_base + wn * 32 + nt * 8 + (lane & 3) * 2;
            const float2 s = *reinterpret_cast<const float2*>(scales + o);
            float2 r0, r1;
            r0.x = c[mt][nt][0] * s.x; r0.y = c[mt][nt][1] * s.y;
            r1.x = c[mt][nt][2] * s.x; r1.y = c[mt][nt][3] * s.y;
            *reinterpret_cast<float2*>(out + (size_t)m0 * OO + o) = r0;
            *reinterpret_cast<float2*>(out + (size_t)(m0 + 8) * OO + o) = r1;
        }
    }
}

extern "C" void kernel_launch(void* const* d_in, const int* in_sizes, int n_in,
                              void* d_out, int out_size) {
    const float* x      = (const float*)d_in[0];
    const int*   packed = (const int*)d_in[1];
    const float* scales = (const float*)d_in[2];
    const void*  vals   = (const void*)d_in[3];
    const int*   idx    = (const int*)d_in[4];
    const int*   ptr    = (const int*)d_in[5];
    const float* alpha  = (const float*)d_in[6];
    float* out = (float*)d_out;

    cudaFuncSetAttribute(gemm_kernel, cudaFuncAttributeMaxDynamicSharedMemorySize, SMEM_BYTES);
    sniff_vals<<<1, 128>>>((const unsigned short*)vals);
    prep_kernel<<<2048 + OO, 256>>>(x, vals, idx, ptr, scales, alpha);
    gemm_kernel<<<128, 512, SMEM_BYTES>>>(packed, scales, out);
}